// round 1
// baseline (speedup 1.0000x reference)
#include <cuda_runtime.h>

#define NN 100000
#define NE 1000000
#define D  128
#define R  16
#define TE 64

// Scratch (device globals — no allocation allowed)
__device__ float g_X[(size_t)NN * D];   // layer-1 input (gathered embeddings)
__device__ float g_H[(size_t)NN * D];   // layer-1 output / layer-2 input
__device__ float g_Z[(size_t)NN * D];   // scatter accumulator
__device__ int   g_cnt[NN];
__device__ int   g_sorted[NE];
__device__ int   g_hist[R];
__device__ int   g_base[R + 1];
__device__ int   g_poff[R + 1];
__device__ int   g_cursor[R];

__global__ void k_zero_meta() {
    int i = blockIdx.x * blockDim.x + threadIdx.x;
    if (i < R)  g_hist[i] = 0;
    if (i < NN) g_cnt[i] = 0;
}

__global__ void k_hist(const int* __restrict__ et) {
    int e = blockIdx.x * blockDim.x + threadIdx.x;
    if (e < NE) atomicAdd(&g_hist[et[e]], 1);
}

__global__ void k_scan() {
    int acc = 0, pacc = 0;
    for (int r = 0; r < R; r++) {
        g_base[r] = acc;
        g_poff[r] = pacc;
        g_cursor[r] = acc;
        acc  += g_hist[r];
        pacc += ((g_hist[r] + TE - 1) / TE) * TE;
    }
    g_base[R] = acc;
    g_poff[R] = pacc;
}

__global__ void k_sort(const int* __restrict__ et) {
    int e = blockIdx.x * blockDim.x + threadIdx.x;
    if (e < NE) {
        int pos = atomicAdd(&g_cursor[et[e]], 1);
        g_sorted[pos] = e;
    }
}

__global__ void k_cnt(const int* __restrict__ dst) {
    int e = blockIdx.x * blockDim.x + threadIdx.x;
    if (e < NE) atomicAdd(&g_cnt[dst[e]], 1);
}

__global__ void k_gather(const int* __restrict__ ent, const float* __restrict__ emb) {
    int n = blockIdx.x;
    int t = threadIdx.x;  // 32 threads, 1 float4 each = 128 floats
    const float4* s = (const float4*)(emb + (size_t)ent[n] * D);
    ((float4*)(g_X + (size_t)n * D))[t] = s[t];
}

__global__ void k_zeroZ() {
    size_t i = (size_t)blockIdx.x * blockDim.x + threadIdx.x;
    ((float4*)g_Z)[i] = make_float4(0.f, 0.f, 0.f, 0.f);
}

__device__ __forceinline__ void red_v4(float* p, float a, float b, float c, float d) {
    asm volatile("red.global.add.v4.f32 [%0], {%1,%2,%3,%4};" ::
                 "l"(p), "f"(a), "f"(b), "f"(c), "f"(d) : "memory");
}

// Fused: gather x[src] -> [TE,128]x[128,128] GEMM with W_r -> atomic scatter to Z[dst]
__global__ __launch_bounds__(128) void k_rgemm(int xsel, const float* __restrict__ Wall,
                                               const int* __restrict__ src,
                                               const int* __restrict__ dst) {
    const float* __restrict__ X = xsel ? g_H : g_X;
    __shared__ float As[TE * 33];     // [row][k] padded
    __shared__ float Ws[32 * 128];    // [k][col]
    __shared__ int s_src[TE], s_dst[TE];

    int t0 = blockIdx.x * TE;
    if (t0 >= g_poff[R]) return;
    int r = 0;
    while (t0 >= g_poff[r + 1]) r++;
    int loc = t0 - g_poff[r];
    int sb  = g_base[r];
    int n   = g_hist[r] - loc;
    if (n > TE) n = TE;
    const float* __restrict__ Wr = Wall + (size_t)r * D * D;

    int tid = threadIdx.x;
    if (tid < TE) {
        int sv = -1, dv = -1;
        if (tid < n) {
            int e = g_sorted[sb + loc + tid];
            sv = src[e];
            dv = dst[e];
        }
        s_src[tid] = sv;
        s_dst[tid] = dv;
    }
    __syncthreads();

    float acc[8][8];
#pragma unroll
    for (int i = 0; i < 8; i++)
#pragma unroll
        for (int j = 0; j < 8; j++) acc[i][j] = 0.f;

    int rg = tid >> 4;   // 8 row-groups of 8 rows
    int cg = tid & 15;   // 16 col-groups of 8 cols

    for (int k0 = 0; k0 < D; k0 += 32) {
        // Stage A: 64 rows x 32 k  (512 float4, 4 per thread)
#pragma unroll
        for (int j = 0; j < 4; j++) {
            int id  = tid + 128 * j;
            int row = id >> 3;
            int k4  = (id & 7) * 4;
            float4 v = make_float4(0.f, 0.f, 0.f, 0.f);
            int s = s_src[row];
            if (s >= 0) v = *(const float4*)(X + (size_t)s * D + k0 + k4);
            float* a = As + row * 33 + k4;
            a[0] = v.x; a[1] = v.y; a[2] = v.z; a[3] = v.w;
        }
        // Stage W: 32 k x 128 cols (1024 float4, 8 per thread)
#pragma unroll
        for (int j = 0; j < 8; j++) {
            int id = tid + 128 * j;
            int kk = id >> 5;
            int c4 = (id & 31) * 4;
            *(float4*)(Ws + kk * 128 + c4) = *(const float4*)(Wr + (size_t)(k0 + kk) * D + c4);
        }
        __syncthreads();
#pragma unroll
        for (int k = 0; k < 32; k++) {
            float a[8];
#pragma unroll
            for (int i = 0; i < 8; i++) a[i] = As[(rg * 8 + i) * 33 + k];
            float4 w0 = *(float4*)(Ws + k * 128 + cg * 8);
            float4 w1 = *(float4*)(Ws + k * 128 + cg * 8 + 4);
#pragma unroll
            for (int i = 0; i < 8; i++) {
                acc[i][0] += a[i] * w0.x; acc[i][1] += a[i] * w0.y;
                acc[i][2] += a[i] * w0.z; acc[i][3] += a[i] * w0.w;
                acc[i][4] += a[i] * w1.x; acc[i][5] += a[i] * w1.y;
                acc[i][6] += a[i] * w1.z; acc[i][7] += a[i] * w1.w;
            }
        }
        __syncthreads();
    }

#pragma unroll
    for (int i = 0; i < 8; i++) {
        int dv = s_dst[rg * 8 + i];
        if (dv >= 0) {
            float* p = g_Z + (size_t)dv * D + cg * 8;
            red_v4(p,     acc[i][0], acc[i][1], acc[i][2], acc[i][3]);
            red_v4(p + 4, acc[i][4], acc[i][5], acc[i][6], acc[i][7]);
        }
    }
}

// H[row] = Z[row]/max(cnt,1) + X[row] @ Wroot   (+ReLU)
__global__ __launch_bounds__(128) void k_combine(int xsel, const float* __restrict__ Wroot,
                                                 float* __restrict__ outp, int use_out,
                                                 int relu) {
    const float* __restrict__ X = xsel ? g_H : g_X;
    float* __restrict__ O = use_out ? outp : g_H;
    __shared__ float As[TE * 33];
    __shared__ float Ws[32 * 128];

    int row0 = blockIdx.x * TE;
    int tid  = threadIdx.x;
    int rg = tid >> 4, cg = tid & 15;

    float acc[8][8];
#pragma unroll
    for (int i = 0; i < 8; i++)
#pragma unroll
        for (int j = 0; j < 8; j++) acc[i][j] = 0.f;

    for (int k0 = 0; k0 < D; k0 += 32) {
#pragma unroll
        for (int j = 0; j < 4; j++) {
            int id  = tid + 128 * j;
            int lr  = id >> 3;
            int k4  = (id & 7) * 4;
            int row = row0 + lr;
            float4 v = make_float4(0.f, 0.f, 0.f, 0.f);
            if (row < NN) v = *(const float4*)(X + (size_t)row * D + k0 + k4);
            float* a = As + lr * 33 + k4;
            a[0] = v.x; a[1] = v.y; a[2] = v.z; a[3] = v.w;
        }
#pragma unroll
        for (int j = 0; j < 8; j++) {
            int id = tid + 128 * j;
            int kk = id >> 5;
            int c4 = (id & 31) * 4;
            *(float4*)(Ws + kk * 128 + c4) = *(const float4*)(Wroot + (size_t)(k0 + kk) * D + c4);
        }
        __syncthreads();
#pragma unroll
        for (int k = 0; k < 32; k++) {
            float a[8];
#pragma unroll
            for (int i = 0; i < 8; i++) a[i] = As[(rg * 8 + i) * 33 + k];
            float4 w0 = *(float4*)(Ws + k * 128 + cg * 8);
            float4 w1 = *(float4*)(Ws + k * 128 + cg * 8 + 4);
#pragma unroll
            for (int i = 0; i < 8; i++) {
                acc[i][0] += a[i] * w0.x; acc[i][1] += a[i] * w0.y;
                acc[i][2] += a[i] * w0.z; acc[i][3] += a[i] * w0.w;
                acc[i][4] += a[i] * w1.x; acc[i][5] += a[i] * w1.y;
                acc[i][6] += a[i] * w1.z; acc[i][7] += a[i] * w1.w;
            }
        }
        __syncthreads();
    }

#pragma unroll
    for (int i = 0; i < 8; i++) {
        int row = row0 + rg * 8 + i;
        if (row < NN) {
            int c = g_cnt[row];
            float ic = 1.0f / (float)(c > 1 ? c : 1);
            const float* zp = g_Z + (size_t)row * D + cg * 8;
            float4 z0 = *(const float4*)zp;
            float4 z1 = *(const float4*)(zp + 4);
            float o[8];
            o[0] = acc[i][0] + z0.x * ic; o[1] = acc[i][1] + z0.y * ic;
            o[2] = acc[i][2] + z0.z * ic; o[3] = acc[i][3] + z0.w * ic;
            o[4] = acc[i][4] + z1.x * ic; o[5] = acc[i][5] + z1.y * ic;
            o[6] = acc[i][6] + z1.z * ic; o[7] = acc[i][7] + z1.w * ic;
            if (relu) {
#pragma unroll
                for (int j = 0; j < 8; j++) o[j] = o[j] > 0.f ? o[j] : 0.f;
            }
            float* op = O + (size_t)row * D + cg * 8;
            *(float4*)op       = make_float4(o[0], o[1], o[2], o[3]);
            *(float4*)(op + 4) = make_float4(o[4], o[5], o[6], o[7]);
        }
    }
}

extern "C" void kernel_launch(void* const* d_in, const int* in_sizes, int n_in,
                              void* d_out, int out_size) {
    const int*   entity = (const int*)d_in[0];
    const int*   eidx   = (const int*)d_in[1];
    const int*   etype  = (const int*)d_in[2];
    const float* emb    = (const float*)d_in[4];
    const float* W1     = (const float*)d_in[5];
    const float* root1  = (const float*)d_in[6];
    const float* W2     = (const float*)d_in[7];
    const float* root2  = (const float*)d_in[8];
    const int* src = eidx;
    const int* dst = eidx + NE;
    float* out = (float*)d_out;

    int gE = (NE + 255) / 256;
    int gN = (NN + 255) / 256;
    int gZ = (NN * D / 4) / 256;            // 12500 exact
    int G  = NE / TE + R;                   // worst-case padded tile count
    int gC = (NN + TE - 1) / TE;

    k_zero_meta<<<gN, 256>>>();
    k_hist<<<gE, 256>>>(etype);
    k_scan<<<1, 1>>>();
    k_sort<<<gE, 256>>>(etype);
    k_cnt<<<gE, 256>>>(dst);
    k_gather<<<NN, 32>>>(entity, emb);

    // Layer 1
    k_zeroZ<<<gZ, 256>>>();
    k_rgemm<<<G, 128>>>(0, W1, src, dst);
    k_combine<<<gC, 128>>>(0, root1, out, 0, 1);

    // Layer 2
    k_zeroZ<<<gZ, 256>>>();
    k_rgemm<<<G, 128>>>(1, W2, src, dst);
    k_combine<<<gC, 128>>>(1, root2, out, 1, 0);
}

// round 4
// speedup vs baseline: 1.5178x; 1.5178x over previous
#include <cuda_runtime.h>
#include <cuda_bf16.h>
#include <cstdint>

#define NN 100000
#define NE 1000000
#define D  128
#define R  16
#define TE 128   // edges (or node rows) per MMA tile

// ---------------- device scratch (no allocation allowed) ----------------
__device__ float g_Z[(size_t)NN * D];
__device__ __nv_bfloat16 g_Xhi[(size_t)NN * D];
__device__ __nv_bfloat16 g_Xlo[(size_t)NN * D];
__device__ __nv_bfloat16 g_Hhi[(size_t)NN * D];
__device__ __nv_bfloat16 g_Hlo[(size_t)NN * D];
__device__ __nv_bfloat16 g_WThi[2][R * D * D];   // [layer][r][n][k] = W[k][n]
__device__ __nv_bfloat16 g_WTlo[2][R * D * D];
__device__ __nv_bfloat16 g_rootThi[2][D * D];
__device__ __nv_bfloat16 g_rootTlo[2][D * D];
__device__ int g_cnt[NN];
__device__ int g_sorted[NE];
__device__ int g_hist[R];
__device__ int g_base[R + 1];
__device__ int g_poff[R + 1];
__device__ int g_cursor[R];

// smem map (bytes). Row pitch 272B (128 bf16 + 8 pad) for conflict-free ldmatrix.
#define SA_HI   0
#define SA_LO   34816
#define SW_HI   69632
#define SW_LO   104448
#define SM_SRC  139264
#define SM_DST  139776
#define SMEM_SZ 140288
// epilogue fp32 D tile reuses [SA_HI, SA_HI+67584) ; pitch 132 floats

// ---------------- helpers ----------------
__device__ __forceinline__ uint32_t smem_u32(const void* p) {
    uint32_t a;
    asm("{ .reg .u64 t; cvta.to.shared.u64 t, %1; cvt.u32.u64 %0, t; }" : "=r"(a) : "l"(p));
    return a;
}
__device__ __forceinline__ void red_v4(float* p, float a, float b, float c, float d) {
    asm volatile("red.global.add.v4.f32 [%0], {%1,%2,%3,%4};" ::
                 "l"(p), "f"(a), "f"(b), "f"(c), "f"(d) : "memory");
}
__device__ __forceinline__ void ldsm4(uint32_t addr, uint32_t& r0, uint32_t& r1,
                                      uint32_t& r2, uint32_t& r3) {
    asm volatile("ldmatrix.sync.aligned.m8n8.x4.shared.b16 {%0,%1,%2,%3}, [%4];"
                 : "=r"(r0), "=r"(r1), "=r"(r2), "=r"(r3) : "r"(addr));
}
__device__ __forceinline__ void mma16816(float* d, const uint32_t* a, uint32_t b0, uint32_t b1) {
    asm volatile(
        "mma.sync.aligned.m16n8k16.row.col.f32.bf16.bf16.f32 "
        "{%0,%1,%2,%3}, {%4,%5,%6,%7}, {%8,%9}, {%0,%1,%2,%3};"
        : "+f"(d[0]), "+f"(d[1]), "+f"(d[2]), "+f"(d[3])
        : "r"(a[0]), "r"(a[1]), "r"(a[2]), "r"(a[3]), "r"(b0), "r"(b1));
}

// split-precision 128x128x128 mainloop; warp w = (mw= w>>1 -> rows mw*32..+31,
// nw = w&1 -> cols nw*64..+63). acc[a][j][4]: a = m16 half, j = n8 tile (8).
__device__ __forceinline__ void mma_main(uint32_t sbase, float acc[2][8][4], int w, int lane) {
    const int mw = w >> 1, nw = w & 1;
    const int rsel = ((lane >> 3) & 1) * 8 + (lane & 7);
    const int ksel = (lane >> 4) * 16;     // bytes within k16 (second 8-k half)
#pragma unroll
    for (int kk = 0; kk < 8; kk++) {
        const int kb = kk * 32 + ksel;
        uint32_t aH[2][4], aL[2][4];
#pragma unroll
        for (int a = 0; a < 2; a++) {
            uint32_t ro = (uint32_t)(mw * 32 + a * 16 + rsel) * 272 + kb;
            ldsm4(sbase + SA_HI + ro, aH[a][0], aH[a][1], aH[a][2], aH[a][3]);
            ldsm4(sbase + SA_LO + ro, aL[a][0], aL[a][1], aL[a][2], aL[a][3]);
        }
#pragma unroll
        for (int p = 0; p < 4; p++) {
            uint32_t wo = (uint32_t)(nw * 64 + p * 16 + rsel) * 272 + kb;
            uint32_t bh[4], bl[4];
            ldsm4(sbase + SW_HI + wo, bh[0], bh[1], bh[2], bh[3]);
            ldsm4(sbase + SW_LO + wo, bl[0], bl[1], bl[2], bl[3]);
#pragma unroll
            for (int a = 0; a < 2; a++) {
                mma16816(acc[a][2 * p],     aH[a], bh[0], bh[2]);
                mma16816(acc[a][2 * p],     aH[a], bl[0], bl[2]);
                mma16816(acc[a][2 * p],     aL[a], bh[0], bh[2]);
                mma16816(acc[a][2 * p + 1], aH[a], bh[1], bh[3]);
                mma16816(acc[a][2 * p + 1], aH[a], bl[1], bl[3]);
                mma16816(acc[a][2 * p + 1], aL[a], bh[1], bh[3]);
            }
        }
    }
}

__device__ __forceinline__ void store_acc_sD(float* sD, float acc[2][8][4], int w, int lane) {
    const int mw = w >> 1, nw = w & 1;
    const int g = lane >> 2, tig = lane & 3;
#pragma unroll
    for (int a = 0; a < 2; a++)
#pragma unroll
        for (int j = 0; j < 8; j++) {
            int row = mw * 32 + a * 16 + g;
            int col = nw * 64 + j * 8 + 2 * tig;
            *(float2*)(sD + row * 132 + col)       = make_float2(acc[a][j][0], acc[a][j][1]);
            *(float2*)(sD + (row + 8) * 132 + col) = make_float2(acc[a][j][2], acc[a][j][3]);
        }
}

// ---------------- setup kernels ----------------
__global__ void k_zero_meta() {
    int i = blockIdx.x * blockDim.x + threadIdx.x;
    if (i < R)  g_hist[i] = 0;
    if (i < NN) g_cnt[i] = 0;
}

__global__ void k_hist(const int* __restrict__ et, const int* __restrict__ dst) {
    __shared__ int sh[R];
    if (threadIdx.x < R) sh[threadIdx.x] = 0;
    __syncthreads();
    int e = blockIdx.x * blockDim.x + threadIdx.x;
    if (e < NE) {
        atomicAdd(&sh[et[e]], 1);
        atomicAdd(&g_cnt[dst[e]], 1);
    }
    __syncthreads();
    if (threadIdx.x < R && sh[threadIdx.x]) atomicAdd(&g_hist[threadIdx.x], sh[threadIdx.x]);
}

__global__ void k_scan() {
    int acc = 0, pacc = 0;
    for (int r = 0; r < R; r++) {
        g_base[r] = acc;
        g_poff[r] = pacc;
        g_cursor[r] = acc;
        acc  += g_hist[r];
        pacc += ((g_hist[r] + TE - 1) / TE) * TE;
    }
    g_base[R] = acc;
    g_poff[R] = pacc;
}

__global__ void k_sort(const int* __restrict__ et) {
    __shared__ int lh[R], lb[R];
    if (threadIdx.x < R) lh[threadIdx.x] = 0;
    __syncthreads();
    int e = blockIdx.x * blockDim.x + threadIdx.x;
    int t = -1, lp = 0;
    if (e < NE) {
        t = et[e];
        lp = atomicAdd(&lh[t], 1);
    }
    __syncthreads();
    if (threadIdx.x < R && lh[threadIdx.x] > 0)
        lb[threadIdx.x] = atomicAdd(&g_cursor[threadIdx.x], lh[threadIdx.x]);
    __syncthreads();
    if (t >= 0) g_sorted[lb[t] + lp] = e;
}

// transpose + bf16 split: relation mats (bx 0..31) and root mats (bx 32,33)
__global__ void k_prepW(const float* __restrict__ W1, const float* __restrict__ W2,
                        const float* __restrict__ root1, const float* __restrict__ root2) {
    int bx = blockIdx.x;
    const float* W;
    __nv_bfloat16 *hi, *lo;
    if (bx < 32) {
        int layer = bx >> 4, r = bx & 15;
        W  = (layer ? W2 : W1) + (size_t)r * D * D;
        hi = g_WThi[layer] + (size_t)r * D * D;
        lo = g_WTlo[layer] + (size_t)r * D * D;
    } else {
        int layer = bx - 32;
        W  = layer ? root2 : root1;
        hi = g_rootThi[layer];
        lo = g_rootTlo[layer];
    }
    for (int idx = threadIdx.x; idx < D * D; idx += blockDim.x) {
        int n = idx >> 7, k = idx & 127;
        float v = W[k * D + n];
        __nv_bfloat16 h = __float2bfloat16(v);
        hi[idx] = h;
        lo[idx] = __float2bfloat16(v - __bfloat162float(h));
    }
}

__global__ void k_gather(const int* __restrict__ ent, const float* __restrict__ emb) {
    int n = blockIdx.x;
    int t = threadIdx.x;  // 32 threads, 4 floats each
    float4 v = ((const float4*)(emb + (size_t)ent[n] * D))[t];
    float f[4] = {v.x, v.y, v.z, v.w};
    __nv_bfloat16 h[4], l[4];
#pragma unroll
    for (int j = 0; j < 4; j++) {
        h[j] = __float2bfloat16(f[j]);
        l[j] = __float2bfloat16(f[j] - __bfloat162float(h[j]));
    }
    *(uint2*)(g_Xhi + (size_t)n * D + t * 4) = *(uint2*)h;
    *(uint2*)(g_Xlo + (size_t)n * D + t * 4) = *(uint2*)l;
}

__global__ void k_zeroZ() {
    size_t i = (size_t)blockIdx.x * blockDim.x + threadIdx.x;
    ((float4*)g_Z)[i] = make_float4(0.f, 0.f, 0.f, 0.f);
}

// ---------------- edge GEMM + scatter (tensor cores via mma.sync) ----------------
__global__ __launch_bounds__(256, 1)
void k_rgemm_mma(int layer, const int* __restrict__ src, const int* __restrict__ dst) {
    extern __shared__ unsigned char sm[];
    uint32_t sbase = smem_u32(sm);
    int tid = threadIdx.x, w = tid >> 5, lane = tid & 31;

    int t0 = blockIdx.x * TE;
    if (t0 >= g_poff[R]) return;
    int r = 0;
    while (t0 >= g_poff[r + 1]) r++;
    int loc = t0 - g_poff[r];
    int sb  = g_base[r];
    int n   = g_hist[r] - loc;
    if (n > TE) n = TE;

    int* s_src = (int*)(sm + SM_SRC);
    int* s_dst = (int*)(sm + SM_DST);
    if (tid < TE) {
        int sv = -1, dv = -1;
        if (tid < n) {
            int e = g_sorted[sb + loc + tid];
            sv = src[e];
            dv = dst[e];
        }
        s_src[tid] = sv;
        s_dst[tid] = dv;
    }

    // stage W hi/lo (rows = n, k contiguous), pitch 272B
    const uint4* Whi = (const uint4*)(g_WThi[layer] + (size_t)r * D * D);
    const uint4* Wlo = (const uint4*)(g_WTlo[layer] + (size_t)r * D * D);
#pragma unroll
    for (int j = 0; j < 8; j++) {
        int id = tid + 256 * j;
        uint32_t off = (uint32_t)(id >> 4) * 272 + (uint32_t)(id & 15) * 16;
        *(uint4*)(sm + SW_HI + off) = Whi[id];
        *(uint4*)(sm + SW_LO + off) = Wlo[id];
    }
    __syncthreads();

    // stage A hi/lo (gathered source rows)
    const __nv_bfloat16* Xhi = layer ? g_Hhi : g_Xhi;
    const __nv_bfloat16* Xlo = layer ? g_Hlo : g_Xlo;
#pragma unroll
    for (int j = 0; j < 8; j++) {
        int id = tid + 256 * j;
        int row = id >> 4, c = id & 15;
        int s = s_src[row];
        uint4 vh = make_uint4(0, 0, 0, 0), vl = make_uint4(0, 0, 0, 0);
        if (s >= 0) {
            vh = ((const uint4*)(Xhi + (size_t)s * D))[c];
            vl = ((const uint4*)(Xlo + (size_t)s * D))[c];
        }
        uint32_t off = (uint32_t)row * 272 + (uint32_t)c * 16;
        *(uint4*)(sm + SA_HI + off) = vh;
        *(uint4*)(sm + SA_LO + off) = vl;
    }
    __syncthreads();

    float acc[2][8][4];
#pragma unroll
    for (int a = 0; a < 2; a++)
#pragma unroll
        for (int j = 0; j < 8; j++)
#pragma unroll
            for (int q = 0; q < 4; q++) acc[a][j][q] = 0.f;

    mma_main(sbase, acc, w, lane);

    __syncthreads();            // done reading A region
    float* sD = (float*)sm;     // 128 x 132 fp32
    store_acc_sD(sD, acc, w, lane);
    __syncthreads();

    // row-contiguous vector-red scatter
#pragma unroll
    for (int i = 0; i < 16; i++) {
        int idx = tid + 256 * i;
        int row = idx >> 5, c = idx & 31;
        int dv = s_dst[row];
        if (dv >= 0) {
            float4 v = *(float4*)(sD + row * 132 + c * 4);
            red_v4(g_Z + (size_t)dv * D + c * 4, v.x, v.y, v.z, v.w);
        }
    }
}

// ---------------- combine: out = Z/max(cnt,1) + X @ root (+ReLU + re-split) ----------------
__global__ __launch_bounds__(256, 1)
void k_combine_mma(int layer, float* __restrict__ outp, int use_out) {
    extern __shared__ unsigned char sm[];
    uint32_t sbase = smem_u32(sm);
    int tid = threadIdx.x, w = tid >> 5, lane = tid & 31;
    int t0 = blockIdx.x * TE;

    const uint4* Whi = (const uint4*)g_rootThi[layer];
    const uint4* Wlo = (const uint4*)g_rootTlo[layer];
#pragma unroll
    for (int j = 0; j < 8; j++) {
        int id = tid + 256 * j;
        uint32_t off = (uint32_t)(id >> 4) * 272 + (uint32_t)(id & 15) * 16;
        *(uint4*)(sm + SW_HI + off) = Whi[id];
        *(uint4*)(sm + SW_LO + off) = Wlo[id];
    }
    const __nv_bfloat16* Xhi = layer ? g_Hhi : g_Xhi;
    const __nv_bfloat16* Xlo = layer ? g_Hlo : g_Xlo;
#pragma unroll
    for (int j = 0; j < 8; j++) {
        int id = tid + 256 * j;
        int row = id >> 4, c = id & 15;
        int grow = t0 + row;
        uint4 vh = make_uint4(0, 0, 0, 0), vl = make_uint4(0, 0, 0, 0);
        if (grow < NN) {
            vh = ((const uint4*)(Xhi + (size_t)grow * D))[c];
            vl = ((const uint4*)(Xlo + (size_t)grow * D))[c];
        }
        uint32_t off = (uint32_t)row * 272 + (uint32_t)c * 16;
        *(uint4*)(sm + SA_HI + off) = vh;
        *(uint4*)(sm + SA_LO + off) = vl;
    }
    __syncthreads();

    float acc[2][8][4];
#pragma unroll
    for (int a = 0; a < 2; a++)
#pragma unroll
        for (int j = 0; j < 8; j++)
#pragma unroll
            for (int q = 0; q < 4; q++) acc[a][j][q] = 0.f;

    mma_main(sbase, acc, w, lane);

    __syncthreads();
    float* sD = (float*)sm;
    store_acc_sD(sD, acc, w, lane);
    __syncthreads();

#pragma unroll
    for (int i = 0; i < 16; i++) {
        int idx = tid + 256 * i;
        int row = idx >> 5, c = idx & 31;
        int grow = t0 + row;
        if (grow < NN) {
            float4 v = *(float4*)(sD + row * 132 + c * 4);
            float4 z = *(const float4*)(g_Z + (size_t)grow * D + c * 4);
            int cc = g_cnt[grow];
            float ic = 1.0f / (float)(cc > 1 ? cc : 1);
            float o[4] = {v.x + z.x * ic, v.y + z.y * ic, v.z + z.z * ic, v.w + z.w * ic};
            if (use_out) {
                *(float4*)(outp + (size_t)grow * D + c * 4) = make_float4(o[0], o[1], o[2], o[3]);
            } else {
                __nv_bfloat16 hh[4], ll[4];
#pragma unroll
                for (int q = 0; q < 4; q++) {
                    o[q] = o[q] > 0.f ? o[q] : 0.f;   // ReLU (layer 1)
                    hh[q] = __float2bfloat16(o[q]);
                    ll[q] = __float2bfloat16(o[q] - __bfloat162float(hh[q]));
                }
                *(uint2*)(g_Hhi + (size_t)grow * D + c * 4) = *(uint2*)hh;
                *(uint2*)(g_Hlo + (size_t)grow * D + c * 4) = *(uint2*)ll;
            }
        }
    }
}

// ---------------- host ----------------
extern "C" void kernel_launch(void* const* d_in, const int* in_sizes, int n_in,
                              void* d_out, int out_size) {
    const int*   entity = (const int*)d_in[0];
    const int*   eidx   = (const int*)d_in[1];
    const int*   etype  = (const int*)d_in[2];
    const float* emb    = (const float*)d_in[4];
    const float* W1     = (const float*)d_in[5];
    const float* root1  = (const float*)d_in[6];
    const float* W2     = (const float*)d_in[7];
    const float* root2  = (const float*)d_in[8];
    const int* src = eidx;
    const int* dst = eidx + NE;
    float* out = (float*)d_out;

    static int attr_done = 0;
    if (!attr_done) {
        cudaFuncSetAttribute(k_rgemm_mma,   cudaFuncAttributeMaxDynamicSharedMemorySize, SMEM_SZ);
        cudaFuncSetAttribute(k_combine_mma, cudaFuncAttributeMaxDynamicSharedMemorySize, SMEM_SZ);
        attr_done = 1;
    }

    int gE = (NE + 255) / 256;
    int gN = (NN + 255) / 256;
    int gZ = (NN * D / 4) / 256;
    int G  = NE / TE + R;
    int gC = (NN + TE - 1) / TE;

    k_zero_meta<<<gN, 256>>>();
    k_hist<<<gE, 256>>>(etype, dst);
    k_scan<<<1, 1>>>();
    k_sort<<<gE, 256>>>(etype);
    k_prepW<<<34, 256>>>(W1, W2, root1, root2);
    k_gather<<<NN, 32>>>(entity, emb);

    // Layer 1
    k_zeroZ<<<gZ, 256>>>();
    k_rgemm_mma<<<G, 256, SMEM_SZ>>>(0, src, dst);
    k_combine_mma<<<gC, 256, SMEM_SZ>>>(0, out, 0);

    // Layer 2
    k_zeroZ<<<gZ, 256>>>();
    k_rgemm_mma<<<G, 256, SMEM_SZ>>>(1, src, dst);
    k_combine_mma<<<gC, 256, SMEM_SZ>>>(1, out, 1);
}

// round 5
// speedup vs baseline: 1.7273x; 1.1380x over previous
#include <cuda_runtime.h>
#include <cuda_bf16.h>
#include <cstdint>

#define NN 100000
#define NE 1000000
#define D  128
#define R  16
#define TE 128   // edges per MMA tile
#define NB 9     // blocks per relation (grid = R*NB = 144)

// ---------------- device scratch (no allocation allowed) ----------------
__device__ float g_Z[(size_t)NN * D];
__device__ __nv_bfloat16 g_Xhi[(size_t)NN * D];
__device__ __nv_bfloat16 g_Xlo[(size_t)NN * D];
__device__ __nv_bfloat16 g_Hhi[(size_t)NN * D];
__device__ __nv_bfloat16 g_Hlo[(size_t)NN * D];
__device__ __nv_bfloat16 g_WThi[2][R * D * D];   // [layer][r][n][k] = W[k][n]
__device__ __nv_bfloat16 g_WTlo[2][R * D * D];
__device__ __nv_bfloat16 g_rootThi[2][D * D];
__device__ __nv_bfloat16 g_rootTlo[2][D * D];
__device__ int g_cnt[NN];
__device__ int g_sorted[NE];
__device__ int g_hist[R];
__device__ int g_base[R + 1];
__device__ int g_cursor[R];

// ---- persistent rgemm smem map (row pitch 272B = 128 bf16 + 8 pad) ----
#define PITCH   272
#define HALF    34816            // 128 rows * 272
#define SW      0                // W hi at 0, W lo at +HALF
#define SA0     69632            // A buf0: hi +0, lo +HALF
#define SA1     139264           // A buf1
#define SMEM_RG 208896

// ---- combine smem map (as round 4) ----
#define SA_HI   0
#define SA_LO   34816
#define SW_HI   69632
#define SW_LO   104448
#define SMEM_CB 140288

// ---------------- helpers ----------------
__device__ __forceinline__ uint32_t smem_u32(const void* p) {
    uint32_t a;
    asm("{ .reg .u64 t; cvta.to.shared.u64 t, %1; cvt.u32.u64 %0, t; }" : "=r"(a) : "l"(p));
    return a;
}
__device__ __forceinline__ void red_v2(float* p, float a, float b) {
    asm volatile("red.global.add.v2.f32 [%0], {%1,%2};" :: "l"(p), "f"(a), "f"(b) : "memory");
}
__device__ __forceinline__ void red_v4(float* p, float a, float b, float c, float d) {
    asm volatile("red.global.add.v4.f32 [%0], {%1,%2,%3,%4};" ::
                 "l"(p), "f"(a), "f"(b), "f"(c), "f"(d) : "memory");
}
__device__ __forceinline__ void ldsm4(uint32_t addr, uint32_t& r0, uint32_t& r1,
                                      uint32_t& r2, uint32_t& r3) {
    asm volatile("ldmatrix.sync.aligned.m8n8.x4.shared.b16 {%0,%1,%2,%3}, [%4];"
                 : "=r"(r0), "=r"(r1), "=r"(r2), "=r"(r3) : "r"(addr));
}
__device__ __forceinline__ void mma16816(float* d, const uint32_t* a, uint32_t b0, uint32_t b1) {
    asm volatile(
        "mma.sync.aligned.m16n8k16.row.col.f32.bf16.bf16.f32 "
        "{%0,%1,%2,%3}, {%4,%5,%6,%7}, {%8,%9}, {%0,%1,%2,%3};"
        : "+f"(d[0]), "+f"(d[1]), "+f"(d[2]), "+f"(d[3])
        : "r"(a[0]), "r"(a[1]), "r"(a[2]), "r"(a[3]), "r"(b0), "r"(b1));
}
__device__ __forceinline__ void cp16(uint32_t saddr, const void* gaddr, int sz) {
    asm volatile("cp.async.cg.shared.global [%0], [%1], 16, %2;"
                 :: "r"(saddr), "l"(gaddr), "r"(sz) : "memory");
}
__device__ __forceinline__ void cp_commit() { asm volatile("cp.async.commit_group;" ::: "memory"); }

// split-precision 128x128x128 mainloop (A at abase: hi+0/lo+HALF; W at wbase likewise)
__device__ __forceinline__ void mma_main(uint32_t wbase, uint32_t abase,
                                         float acc[2][8][4], int mw, int nw, int lane) {
    const int rsel = ((lane >> 3) & 1) * 8 + (lane & 7);
    const int ksel = (lane >> 4) * 16;
#pragma unroll
    for (int kk = 0; kk < 8; kk++) {
        const int kb = kk * 32 + ksel;
        uint32_t aH[2][4], aL[2][4];
#pragma unroll
        for (int a = 0; a < 2; a++) {
            uint32_t ro = (uint32_t)(mw * 32 + a * 16 + rsel) * PITCH + kb;
            ldsm4(abase + ro, aH[a][0], aH[a][1], aH[a][2], aH[a][3]);
            ldsm4(abase + HALF + ro, aL[a][0], aL[a][1], aL[a][2], aL[a][3]);
        }
#pragma unroll
        for (int p = 0; p < 4; p++) {
            uint32_t wo = (uint32_t)(nw * 64 + p * 16 + rsel) * PITCH + kb;
            uint32_t bh[4], bl[4];
            ldsm4(wbase + wo, bh[0], bh[1], bh[2], bh[3]);
            ldsm4(wbase + HALF + wo, bl[0], bl[1], bl[2], bl[3]);
#pragma unroll
            for (int a = 0; a < 2; a++) {
                mma16816(acc[a][2 * p],     aH[a], bh[0], bh[2]);
                mma16816(acc[a][2 * p],     aH[a], bl[0], bl[2]);
                mma16816(acc[a][2 * p],     aL[a], bh[0], bh[2]);
                mma16816(acc[a][2 * p + 1], aH[a], bh[1], bh[3]);
                mma16816(acc[a][2 * p + 1], aH[a], bl[1], bl[3]);
                mma16816(acc[a][2 * p + 1], aL[a], bh[1], bh[3]);
            }
        }
    }
}

// ---------------- setup kernels ----------------
__global__ void k_zero_meta() {
    int i = blockIdx.x * blockDim.x + threadIdx.x;
    if (i < R)  g_hist[i] = 0;
    if (i < NN) g_cnt[i] = 0;
}

__global__ void k_hist(const int* __restrict__ et, const int* __restrict__ dst) {
    __shared__ int sh[R];
    if (threadIdx.x < R) sh[threadIdx.x] = 0;
    __syncthreads();
    int e = blockIdx.x * blockDim.x + threadIdx.x;
    if (e < NE) {
        atomicAdd(&sh[et[e]], 1);
        atomicAdd(&g_cnt[dst[e]], 1);
    }
    __syncthreads();
    if (threadIdx.x < R && sh[threadIdx.x]) atomicAdd(&g_hist[threadIdx.x], sh[threadIdx.x]);
}

__global__ void k_scan() {
    int acc = 0;
    for (int r = 0; r < R; r++) {
        g_base[r] = acc;
        g_cursor[r] = acc;
        acc += g_hist[r];
    }
    g_base[R] = acc;
}

__global__ void k_sort(const int* __restrict__ et) {
    __shared__ int lh[R], lb[R];
    if (threadIdx.x < R) lh[threadIdx.x] = 0;
    __syncthreads();
    int e = blockIdx.x * blockDim.x + threadIdx.x;
    int t = -1, lp = 0;
    if (e < NE) {
        t = et[e];
        lp = atomicAdd(&lh[t], 1);
    }
    __syncthreads();
    if (threadIdx.x < R && lh[threadIdx.x] > 0)
        lb[threadIdx.x] = atomicAdd(&g_cursor[threadIdx.x], lh[threadIdx.x]);
    __syncthreads();
    if (t >= 0) g_sorted[lb[t] + lp] = e;
}

__global__ void k_prepW(const float* __restrict__ W1, const float* __restrict__ W2,
                        const float* __restrict__ root1, const float* __restrict__ root2) {
    int bx = blockIdx.x;
    const float* W;
    __nv_bfloat16 *hi, *lo;
    if (bx < 32) {
        int layer = bx >> 4, r = bx & 15;
        W  = (layer ? W2 : W1) + (size_t)r * D * D;
        hi = g_WThi[layer] + (size_t)r * D * D;
        lo = g_WTlo[layer] + (size_t)r * D * D;
    } else {
        int layer = bx - 32;
        W  = layer ? root2 : root1;
        hi = g_rootThi[layer];
        lo = g_rootTlo[layer];
    }
    for (int idx = threadIdx.x; idx < D * D; idx += blockDim.x) {
        int n = idx >> 7, k = idx & 127;
        float v = W[k * D + n];
        __nv_bfloat16 h = __float2bfloat16(v);
        hi[idx] = h;
        lo[idx] = __float2bfloat16(v - __bfloat162float(h));
    }
}

__global__ void k_gather(const int* __restrict__ ent, const float* __restrict__ emb) {
    int id = blockIdx.x * blockDim.x + threadIdx.x;
    int n = id >> 5, t = id & 31;
    float4 v = ((const float4*)(emb + (size_t)ent[n] * D))[t];
    float f[4] = {v.x, v.y, v.z, v.w};
    __nv_bfloat16 h[4], l[4];
#pragma unroll
    for (int j = 0; j < 4; j++) {
        h[j] = __float2bfloat16(f[j]);
        l[j] = __float2bfloat16(f[j] - __bfloat162float(h[j]));
    }
    *(uint2*)(g_Xhi + (size_t)n * D + t * 4) = *(uint2*)h;
    *(uint2*)(g_Xlo + (size_t)n * D + t * 4) = *(uint2*)l;
}

__global__ void k_zeroZ() {
    size_t i = (size_t)blockIdx.x * blockDim.x + threadIdx.x;
    ((float4*)g_Z)[i] = make_float4(0.f, 0.f, 0.f, 0.f);
}

// ---------------- persistent edge GEMM + scatter ----------------
__device__ __forceinline__ void issue_A(const __nv_bfloat16* __restrict__ Xhi,
                                        const __nv_bfloat16* __restrict__ Xlo,
                                        const int* __restrict__ src,
                                        int ebase, int n, uint32_t abase, int tid) {
#pragma unroll
    for (int j = 0; j < 8; j++) {
        int id = tid + 256 * j;
        int row = id >> 4, c = id & 15;
        const void* gh = Xhi;
        const void* gl = Xlo;
        int sz = 0;
        if (row < n) {
            int e = g_sorted[ebase + row];
            int s = src[e];
            gh = (const uint4*)(Xhi + (size_t)s * D) + c;
            gl = (const uint4*)(Xlo + (size_t)s * D) + c;
            sz = 16;
        }
        uint32_t off = (uint32_t)row * PITCH + (uint32_t)c * 16;
        cp16(abase + off, gh, sz);
        cp16(abase + HALF + off, gl, sz);
    }
}

__global__ __launch_bounds__(256, 1)
void k_rgemm_mma(int layer, const int* __restrict__ src, const int* __restrict__ dst) {
    extern __shared__ unsigned char sm[];
    uint32_t sbase = smem_u32(sm);
    int tid = threadIdx.x, w = tid >> 5, lane = tid & 31;
    const int mw = w >> 1, nw = w & 1;

    int r = blockIdx.x / NB;
    int j = blockIdx.x % NB;
    int hist = g_hist[r];
    int sb   = g_base[r];
    int Tr   = (hist + TE - 1) / TE;
    int per  = (Tr + NB - 1) / NB;
    int tb   = j * per;
    int te   = tb + per;
    if (te > Tr) te = Tr;
    int nt = te - tb;
    if (nt <= 0) return;

    // stage W_r hi/lo once (plain LDG->STS)
    const uint4* Whi = (const uint4*)(g_WThi[layer] + (size_t)r * D * D);
    const uint4* Wlo = (const uint4*)(g_WTlo[layer] + (size_t)r * D * D);
#pragma unroll
    for (int q = 0; q < 8; q++) {
        int id = tid + 256 * q;
        uint32_t off = (uint32_t)(id >> 4) * PITCH + (uint32_t)(id & 15) * 16;
        *(uint4*)(sm + SW + off) = Whi[id];
        *(uint4*)(sm + SW + HALF + off) = Wlo[id];
    }

    const __nv_bfloat16* Xhi = layer ? g_Hhi : g_Xhi;
    const __nv_bfloat16* Xlo = layer ? g_Hlo : g_Xlo;

    // prologue: prefetch tiles tb, tb+1
    {
        int n0 = hist - tb * TE; if (n0 > TE) n0 = TE;
        issue_A(Xhi, Xlo, src, sb + tb * TE, n0, sbase + SA0, tid);
        cp_commit();
        if (nt > 1) {
            int n1 = hist - (tb + 1) * TE; if (n1 > TE) n1 = TE;
            issue_A(Xhi, Xlo, src, sb + (tb + 1) * TE, n1, sbase + SA1, tid);
            cp_commit();
        }
    }

    const int g = lane >> 2, tig = lane & 3;

    for (int ti = 0; ti < nt; ti++) {
        int t = tb + ti;
        int ebase = sb + t * TE;
        int n = hist - t * TE; if (n > TE) n = TE;
        uint32_t abase = sbase + ((ti & 1) ? SA1 : SA0);

        if (ti + 1 < nt) asm volatile("cp.async.wait_group 1;" ::: "memory");
        else             asm volatile("cp.async.wait_group 0;" ::: "memory");
        __syncthreads();

        float acc[2][8][4];
#pragma unroll
        for (int a = 0; a < 2; a++)
#pragma unroll
            for (int q = 0; q < 8; q++)
#pragma unroll
                for (int z = 0; z < 4; z++) acc[a][q][z] = 0.f;

        mma_main(sbase + SW, abase, acc, mw, nw, lane);
        __syncthreads();     // all warps done reading this A buffer

        // overlap next-next prefetch with scatter
        if (ti + 2 < nt) {
            int t2 = tb + ti + 2;
            int n2 = hist - t2 * TE; if (n2 > TE) n2 = TE;
            issue_A(Xhi, Xlo, src, sb + t2 * TE, n2, abase, tid);
            cp_commit();
        }

        // scatter from registers: thread owns rows (mw*32 + a*16 + g [+8]), cols nw*64+q*8+2*tig
#pragma unroll
        for (int a = 0; a < 2; a++) {
#pragma unroll
            for (int h = 0; h < 2; h++) {
                int row = mw * 32 + a * 16 + g + h * 8;
                if (row < n) {
                    int e = g_sorted[ebase + row];
                    float* p = g_Z + (size_t)dst[e] * D + nw * 64 + 2 * tig;
#pragma unroll
                    for (int q = 0; q < 8; q++)
                        red_v2(p + q * 8, acc[a][q][2 * h], acc[a][q][2 * h + 1]);
                }
            }
        }
    }
}

// ---------------- combine: out = Z/max(cnt,1) + X @ root (+ReLU + re-split) ----------------
__device__ __forceinline__ void mma_main_cb(uint32_t sbase, float acc[2][8][4], int w, int lane) {
    const int mw = w >> 1, nw = w & 1;
    const int rsel = ((lane >> 3) & 1) * 8 + (lane & 7);
    const int ksel = (lane >> 4) * 16;
#pragma unroll
    for (int kk = 0; kk < 8; kk++) {
        const int kb = kk * 32 + ksel;
        uint32_t aH[2][4], aL[2][4];
#pragma unroll
        for (int a = 0; a < 2; a++) {
            uint32_t ro = (uint32_t)(mw * 32 + a * 16 + rsel) * PITCH + kb;
            ldsm4(sbase + SA_HI + ro, aH[a][0], aH[a][1], aH[a][2], aH[a][3]);
            ldsm4(sbase + SA_LO + ro, aL[a][0], aL[a][1], aL[a][2], aL[a][3]);
        }
#pragma unroll
        for (int p = 0; p < 4; p++) {
            uint32_t wo = (uint32_t)(nw * 64 + p * 16 + rsel) * PITCH + kb;
            uint32_t bh[4], bl[4];
            ldsm4(sbase + SW_HI + wo, bh[0], bh[1], bh[2], bh[3]);
            ldsm4(sbase + SW_LO + wo, bl[0], bl[1], bl[2], bl[3]);
#pragma unroll
            for (int a = 0; a < 2; a++) {
                mma16816(acc[a][2 * p],     aH[a], bh[0], bh[2]);
                mma16816(acc[a][2 * p],     aH[a], bl[0], bl[2]);
                mma16816(acc[a][2 * p],     aL[a], bh[0], bh[2]);
                mma16816(acc[a][2 * p + 1], aH[a], bh[1], bh[3]);
                mma16816(acc[a][2 * p + 1], aH[a], bl[1], bl[3]);
                mma16816(acc[a][2 * p + 1], aL[a], bh[1], bh[3]);
            }
        }
    }
}

__global__ __launch_bounds__(256, 1)
void k_combine_mma(int layer, float* __restrict__ outp, int use_out) {
    extern __shared__ unsigned char sm[];
    uint32_t sbase = smem_u32(sm);
    int tid = threadIdx.x, w = tid >> 5, lane = tid & 31;
    int t0 = blockIdx.x * TE;

    const uint4* Whi = (const uint4*)g_rootThi[layer];
    const uint4* Wlo = (const uint4*)g_rootTlo[layer];
#pragma unroll
    for (int q = 0; q < 8; q++) {
        int id = tid + 256 * q;
        uint32_t off = (uint32_t)(id >> 4) * PITCH + (uint32_t)(id & 15) * 16;
        *(uint4*)(sm + SW_HI + off) = Whi[id];
        *(uint4*)(sm + SW_LO + off) = Wlo[id];
    }
    const __nv_bfloat16* Xhi = layer ? g_Hhi : g_Xhi;
    const __nv_bfloat16* Xlo = layer ? g_Hlo : g_Xlo;
#pragma unroll
    for (int q = 0; q < 8; q++) {
        int id = tid + 256 * q;
        int row = id >> 4, c = id & 15;
        int grow = t0 + row;
        uint4 vh = make_uint4(0, 0, 0, 0), vl = make_uint4(0, 0, 0, 0);
        if (grow < NN) {
            vh = ((const uint4*)(Xhi + (size_t)grow * D))[c];
            vl = ((const uint4*)(Xlo + (size_t)grow * D))[c];
        }
        uint32_t off = (uint32_t)row * PITCH + (uint32_t)c * 16;
        *(uint4*)(sm + SA_HI + off) = vh;
        *(uint4*)(sm + SA_LO + off) = vl;
    }
    __syncthreads();

    float acc[2][8][4];
#pragma unroll
    for (int a = 0; a < 2; a++)
#pragma unroll
        for (int q = 0; q < 8; q++)
#pragma unroll
            for (int z = 0; z < 4; z++) acc[a][q][z] = 0.f;

    mma_main_cb(sbase, acc, w, lane);

    // epilogue directly from registers
    const int mw = w >> 1, nw = w & 1;
    const int g = lane >> 2, tig = lane & 3;
#pragma unroll
    for (int a = 0; a < 2; a++) {
#pragma unroll
        for (int h = 0; h < 2; h++) {
            int grow = t0 + mw * 32 + a * 16 + g + h * 8;
            if (grow < NN) {
                int cc = g_cnt[grow];
                float ic = 1.0f / (float)(cc > 1 ? cc : 1);
#pragma unroll
                for (int q = 0; q < 8; q++) {
                    int col = nw * 64 + q * 8 + 2 * tig;
                    float2 z = *(const float2*)(g_Z + (size_t)grow * D + col);
                    float o0 = acc[a][q][2 * h]     + z.x * ic;
                    float o1 = acc[a][q][2 * h + 1] + z.y * ic;
                    if (use_out) {
                        *(float2*)(outp + (size_t)grow * D + col) = make_float2(o0, o1);
                    } else {
                        o0 = o0 > 0.f ? o0 : 0.f;
                        o1 = o1 > 0.f ? o1 : 0.f;
                        __nv_bfloat16 h0 = __float2bfloat16(o0);
                        __nv_bfloat16 h1 = __float2bfloat16(o1);
                        __nv_bfloat16 l0 = __float2bfloat16(o0 - __bfloat162float(h0));
                        __nv_bfloat16 l1 = __float2bfloat16(o1 - __bfloat162float(h1));
                        __nv_bfloat162 hh; hh.x = h0; hh.y = h1;
                        __nv_bfloat162 ll; ll.x = l0; ll.y = l1;
                        *(__nv_bfloat162*)(g_Hhi + (size_t)grow * D + col) = hh;
                        *(__nv_bfloat162*)(g_Hlo + (size_t)grow * D + col) = ll;
                    }
                }
            }
        }
    }
}

// ---------------- host ----------------
extern "C" void kernel_launch(void* const* d_in, const int* in_sizes, int n_in,
                              void* d_out, int out_size) {
    const int*   entity = (const int*)d_in[0];
    const int*   eidx   = (const int*)d_in[1];
    const int*   etype  = (const int*)d_in[2];
    const float* emb    = (const float*)d_in[4];
    const float* W1     = (const float*)d_in[5];
    const float* root1  = (const float*)d_in[6];
    const float* W2     = (const float*)d_in[7];
    const float* root2  = (const float*)d_in[8];
    const int* src = eidx;
    const int* dst = eidx + NE;
    float* out = (float*)d_out;

    static int attr_done = 0;
    if (!attr_done) {
        cudaFuncSetAttribute(k_rgemm_mma,   cudaFuncAttributeMaxDynamicSharedMemorySize, SMEM_RG);
        cudaFuncSetAttribute(k_combine_mma, cudaFuncAttributeMaxDynamicSharedMemorySize, SMEM_CB);
        attr_done = 1;
    }

    int gE = (NE + 255) / 256;
    int gN = (NN + 255) / 256;
    int gZ = (NN * D / 4) / 256;
    int gC = (NN + TE - 1) / TE;

    k_zero_meta<<<gN, 256>>>();
    k_hist<<<gE, 256>>>(etype, dst);
    k_scan<<<1, 1>>>();
    k_sort<<<gE, 256>>>(etype);
    k_prepW<<<34, 256>>>(W1, W2, root1, root2);
    k_gather<<<NN / 8, 256>>>(entity, emb);

    // Layer 1
    k_zeroZ<<<gZ, 256>>>();
    k_rgemm_mma<<<R * NB, 256, SMEM_RG>>>(0, src, dst);
    k_combine_mma<<<gC, 256, SMEM_CB>>>(0, out, 0);

    // Layer 2
    k_zeroZ<<<gZ, 256>>>();
    k_rgemm_mma<<<R * NB, 256, SMEM_RG>>>(1, src, dst);
    k_combine_mma<<<gC, 256, SMEM_CB>>>(1, out, 1);
}

// round 6
// speedup vs baseline: 2.4974x; 1.4458x over previous
#include <cuda_runtime.h>
#include <cuda_fp16.h>
#include <cstdint>

#define NN 100000
#define NE 1000000
#define D  128
#define R  16
#define TE 128   // edges per MMA tile
#define NB 9     // blocks per relation (grid = R*NB = 144)

// ---------------- device scratch (no allocation allowed) ----------------
__device__ float g_Z[(size_t)NN * D];
__device__ __half g_Xh[(size_t)NN * D];          // layer-1 input, fp16
__device__ __half g_Hh[(size_t)NN * D];          // layer-1 output, fp16
__device__ __half g_WThi[2][R * D * D];          // [layer][r][n][k] = W[k][n], fp16 hi
__device__ __half g_WTlo[2][R * D * D];          // residual
__device__ __half g_rootThi[2][D * D];
__device__ __half g_rootTlo[2][D * D];
__device__ int g_cnt[NN];
__device__ int g_sorted[NE];
__device__ int g_hist[R];
__device__ int g_base[R + 1];
__device__ int g_cursor[R];

// ---- smem maps (row pitch 272B = 256B data + 16B pad; conflict-free ldsm) ----
#define PITCH   272
#define WBLK    34816            // 128 rows * 272
// rgemm: W hi @0, W lo @WBLK, A bufs @ 2*WBLK + i*WBLK (triple buffered)
#define SA_BASE 69632
#define SMEM_RG 174080           // 69632 + 3*34816
// combine: W hi @0, W lo @WBLK, A @ 2*WBLK
#define SMEM_CB 104448

// ---------------- helpers ----------------
__device__ __forceinline__ uint32_t smem_u32(const void* p) {
    uint32_t a;
    asm("{ .reg .u64 t; cvta.to.shared.u64 t, %1; cvt.u32.u64 %0, t; }" : "=r"(a) : "l"(p));
    return a;
}
__device__ __forceinline__ void red_v2(float* p, float a, float b) {
    asm volatile("red.global.add.v2.f32 [%0], {%1,%2};" :: "l"(p), "f"(a), "f"(b) : "memory");
}
__device__ __forceinline__ void ldsm4(uint32_t addr, uint32_t& r0, uint32_t& r1,
                                      uint32_t& r2, uint32_t& r3) {
    asm volatile("ldmatrix.sync.aligned.m8n8.x4.shared.b16 {%0,%1,%2,%3}, [%4];"
                 : "=r"(r0), "=r"(r1), "=r"(r2), "=r"(r3) : "r"(addr));
}
__device__ __forceinline__ void mma16816(float* d, const uint32_t* a, uint32_t b0, uint32_t b1) {
    asm volatile(
        "mma.sync.aligned.m16n8k16.row.col.f32.f16.f16.f32 "
        "{%0,%1,%2,%3}, {%4,%5,%6,%7}, {%8,%9}, {%0,%1,%2,%3};"
        : "+f"(d[0]), "+f"(d[1]), "+f"(d[2]), "+f"(d[3])
        : "r"(a[0]), "r"(a[1]), "r"(a[2]), "r"(a[3]), "r"(b0), "r"(b1));
}
__device__ __forceinline__ void cp16(uint32_t saddr, const void* gaddr, int sz) {
    asm volatile("cp.async.cg.shared.global [%0], [%1], 16, %2;"
                 :: "r"(saddr), "l"(gaddr), "r"(sz) : "memory");
}
__device__ __forceinline__ void cp_commit() { asm volatile("cp.async.commit_group;" ::: "memory"); }

// fp16 2-term 128x128x128 mainloop. W at wbase (hi @0, lo @+WBLK), A at abase.
// warp (mw,nw): rows mw*32..+31, cols nw*64..+63.
__device__ __forceinline__ void mma_main(uint32_t wbase, uint32_t abase,
                                         float acc[2][8][4], int mw, int nw, int lane) {
    const int rsel = ((lane >> 3) & 1) * 8 + (lane & 7);
    const int ksel = (lane >> 4) * 16;
#pragma unroll
    for (int kk = 0; kk < 8; kk++) {
        const int kb = kk * 32 + ksel;
        uint32_t aH[2][4];
#pragma unroll
        for (int a = 0; a < 2; a++) {
            uint32_t ro = (uint32_t)(mw * 32 + a * 16 + rsel) * PITCH + kb;
            ldsm4(abase + ro, aH[a][0], aH[a][1], aH[a][2], aH[a][3]);
        }
#pragma unroll
        for (int p = 0; p < 4; p++) {
            uint32_t wo = (uint32_t)(nw * 64 + p * 16 + rsel) * PITCH + kb;
            uint32_t bh[4], bl[4];
            ldsm4(wbase + wo, bh[0], bh[1], bh[2], bh[3]);
            ldsm4(wbase + WBLK + wo, bl[0], bl[1], bl[2], bl[3]);
#pragma unroll
            for (int a = 0; a < 2; a++) {
                mma16816(acc[a][2 * p],     aH[a], bh[0], bh[2]);
                mma16816(acc[a][2 * p],     aH[a], bl[0], bl[2]);
                mma16816(acc[a][2 * p + 1], aH[a], bh[1], bh[3]);
                mma16816(acc[a][2 * p + 1], aH[a], bl[1], bl[3]);
            }
        }
    }
}

// ---------------- setup kernels ----------------
__global__ void k_zero_meta() {
    int i = blockIdx.x * blockDim.x + threadIdx.x;
    if (i < R)  g_hist[i] = 0;
    if (i < NN) g_cnt[i] = 0;
}

__global__ void k_hist(const int* __restrict__ et, const int* __restrict__ dst) {
    __shared__ int sh[R];
    if (threadIdx.x < R) sh[threadIdx.x] = 0;
    __syncthreads();
    int e = blockIdx.x * blockDim.x + threadIdx.x;
    if (e < NE) {
        atomicAdd(&sh[et[e]], 1);
        atomicAdd(&g_cnt[dst[e]], 1);
    }
    __syncthreads();
    if (threadIdx.x < R && sh[threadIdx.x]) atomicAdd(&g_hist[threadIdx.x], sh[threadIdx.x]);
}

__global__ void k_scan() {
    int acc = 0;
    for (int r = 0; r < R; r++) {
        g_base[r] = acc;
        g_cursor[r] = acc;
        acc += g_hist[r];
    }
    g_base[R] = acc;
}

__global__ void k_sort(const int* __restrict__ et) {
    __shared__ int lh[R], lb[R];
    if (threadIdx.x < R) lh[threadIdx.x] = 0;
    __syncthreads();
    int e = blockIdx.x * blockDim.x + threadIdx.x;
    int t = -1, lp = 0;
    if (e < NE) {
        t = et[e];
        lp = atomicAdd(&lh[t], 1);
    }
    __syncthreads();
    if (threadIdx.x < R && lh[threadIdx.x] > 0)
        lb[threadIdx.x] = atomicAdd(&g_cursor[threadIdx.x], lh[threadIdx.x]);
    __syncthreads();
    if (t >= 0) g_sorted[lb[t] + lp] = e;
}

// transpose + fp16 split: W[k][n] -> WT[n][k] hi/lo; bx 0..31 relations, 32..33 roots
__global__ void k_prepW(const float* __restrict__ W1, const float* __restrict__ W2,
                        const float* __restrict__ root1, const float* __restrict__ root2) {
    int bx = blockIdx.x;
    const float* W;
    __half *hi, *lo;
    if (bx < 32) {
        int layer = bx >> 4, r = bx & 15;
        W  = (layer ? W2 : W1) + (size_t)r * D * D;
        hi = g_WThi[layer] + (size_t)r * D * D;
        lo = g_WTlo[layer] + (size_t)r * D * D;
    } else {
        int layer = bx - 32;
        W  = layer ? root2 : root1;
        hi = g_rootThi[layer];
        lo = g_rootTlo[layer];
    }
    for (int idx = threadIdx.x; idx < D * D; idx += blockDim.x) {
        int n = idx >> 7, k = idx & 127;
        float v = W[k * D + n];
        __half h = __float2half_rn(v);
        hi[idx] = h;
        lo[idx] = __float2half_rn(v - __half2float(h));
    }
}

__global__ void k_gather(const int* __restrict__ ent, const float* __restrict__ emb) {
    int id = blockIdx.x * blockDim.x + threadIdx.x;
    int n = id >> 5, t = id & 31;
    float4 v = ((const float4*)(emb + (size_t)ent[n] * D))[t];
    __half h[4] = {__float2half_rn(v.x), __float2half_rn(v.y),
                   __float2half_rn(v.z), __float2half_rn(v.w)};
    *(uint2*)(g_Xh + (size_t)n * D + t * 4) = *(uint2*)h;
}

__global__ void k_zeroZ() {
    size_t i = (size_t)blockIdx.x * blockDim.x + threadIdx.x;
    ((float4*)g_Z)[i] = make_float4(0.f, 0.f, 0.f, 0.f);
}

// ---------------- persistent edge GEMM + scatter ----------------
__device__ __forceinline__ void issue_A(const __half* __restrict__ Xh,
                                        const int* __restrict__ src,
                                        int ebase, int n, uint32_t abase, int tid) {
#pragma unroll
    for (int j = 0; j < 8; j++) {
        int id = tid + 256 * j;
        int row = id >> 4, c = id & 15;
        const void* g = Xh;
        int sz = 0;
        if (row < n) {
            int e = g_sorted[ebase + row];
            g = (const uint4*)(Xh + (size_t)src[e] * D) + c;
            sz = 16;
        }
        cp16(abase + (uint32_t)row * PITCH + (uint32_t)c * 16, g, sz);
    }
}

__global__ __launch_bounds__(256, 1)
void k_rgemm_mma(int layer, const int* __restrict__ src, const int* __restrict__ dst) {
    extern __shared__ unsigned char sm[];
    uint32_t sbase = smem_u32(sm);
    int tid = threadIdx.x, w = tid >> 5, lane = tid & 31;
    const int mw = w >> 1, nw = w & 1;

    int r = blockIdx.x / NB;
    int j = blockIdx.x % NB;
    int hist = g_hist[r];
    int sb   = g_base[r];
    int Tr   = (hist + TE - 1) / TE;
    int per  = (Tr + NB - 1) / NB;
    int tb   = j * per;
    int te   = tb + per;
    if (te > Tr) te = Tr;
    int nt = te - tb;
    if (nt <= 0) return;

    // stage W_r hi/lo once
    const uint4* Whi = (const uint4*)(g_WThi[layer] + (size_t)r * D * D);
    const uint4* Wlo = (const uint4*)(g_WTlo[layer] + (size_t)r * D * D);
#pragma unroll
    for (int q = 0; q < 8; q++) {
        int id = tid + 256 * q;
        uint32_t off = (uint32_t)(id >> 4) * PITCH + (uint32_t)(id & 15) * 16;
        *(uint4*)(sm + off) = Whi[id];
        *(uint4*)(sm + WBLK + off) = Wlo[id];
    }

    const __half* Xh = layer ? g_Hh : g_Xh;

    // prologue: prefetch tiles tb, tb+1 into bufs 0,1
    {
        int n0 = hist - tb * TE; if (n0 > TE) n0 = TE;
        issue_A(Xh, src, sb + tb * TE, n0, sbase + SA_BASE, tid);
        cp_commit();
        if (nt > 1) {
            int n1 = hist - (tb + 1) * TE; if (n1 > TE) n1 = TE;
            issue_A(Xh, src, sb + (tb + 1) * TE, n1, sbase + SA_BASE + WBLK, tid);
        }
        cp_commit();
    }

    const int g = lane >> 2, tig = lane & 3;
    int buf = 0;

    for (int ti = 0; ti < nt; ti++) {
        int t = tb + ti;
        int ebase = sb + t * TE;
        int n = hist - t * TE; if (n > TE) n = TE;
        uint32_t abase = sbase + SA_BASE + (uint32_t)buf * WBLK;

        asm volatile("cp.async.wait_group 1;" ::: "memory");
        __syncthreads();   // tile ti ready everywhere; all warps past mma of ti-1

        // refill buffer consumed at ti-1 with tile ti+2
        if (ti + 2 < nt) {
            int t2 = tb + ti + 2;
            int n2 = hist - t2 * TE; if (n2 > TE) n2 = TE;
            int b2 = buf + 2; if (b2 >= 3) b2 -= 3;
            issue_A(Xh, src, sb + t2 * TE, n2, sbase + SA_BASE + (uint32_t)b2 * WBLK, tid);
        }
        cp_commit();

        float acc[2][8][4];
#pragma unroll
        for (int a = 0; a < 2; a++)
#pragma unroll
            for (int q = 0; q < 8; q++)
#pragma unroll
                for (int z = 0; z < 4; z++) acc[a][q][z] = 0.f;

        mma_main(sbase, abase, acc, mw, nw, lane);

        // scatter straight from registers
#pragma unroll
        for (int a = 0; a < 2; a++) {
#pragma unroll
            for (int h = 0; h < 2; h++) {
                int row = mw * 32 + a * 16 + g + h * 8;
                if (row < n) {
                    int e = g_sorted[ebase + row];
                    float* p = g_Z + (size_t)dst[e] * D + nw * 64 + 2 * tig;
#pragma unroll
                    for (int q = 0; q < 8; q++)
                        red_v2(p + q * 8, acc[a][q][2 * h], acc[a][q][2 * h + 1]);
                }
            }
        }

        buf++; if (buf == 3) buf = 0;
    }
}

// ---------------- combine: out = Z/max(cnt,1) + X @ root (+ReLU, +fp16 store) ----------------
__global__ __launch_bounds__(256, 1)
void k_combine_mma(int layer, float* __restrict__ outp, int use_out) {
    extern __shared__ unsigned char sm[];
    uint32_t sbase = smem_u32(sm);
    int tid = threadIdx.x, w = tid >> 5, lane = tid & 31;
    const int mw = w >> 1, nw = w & 1;
    int t0 = blockIdx.x * TE;

    const uint4* Whi = (const uint4*)g_rootThi[layer];
    const uint4* Wlo = (const uint4*)g_rootTlo[layer];
#pragma unroll
    for (int q = 0; q < 8; q++) {
        int id = tid + 256 * q;
        uint32_t off = (uint32_t)(id >> 4) * PITCH + (uint32_t)(id & 15) * 16;
        *(uint4*)(sm + off) = Whi[id];
        *(uint4*)(sm + WBLK + off) = Wlo[id];
    }
    const __half* Xh = layer ? g_Hh : g_Xh;
#pragma unroll
    for (int q = 0; q < 8; q++) {
        int id = tid + 256 * q;
        int row = id >> 4, c = id & 15;
        int grow = t0 + row;
        uint4 v = make_uint4(0, 0, 0, 0);
        if (grow < NN) v = ((const uint4*)(Xh + (size_t)grow * D))[c];
        *(uint4*)(sm + 2 * WBLK + (uint32_t)row * PITCH + (uint32_t)c * 16) = v;
    }
    __syncthreads();

    float acc[2][8][4];
#pragma unroll
    for (int a = 0; a < 2; a++)
#pragma unroll
        for (int q = 0; q < 8; q++)
#pragma unroll
            for (int z = 0; z < 4; z++) acc[a][q][z] = 0.f;

    mma_main(sbase, sbase + 2 * WBLK, acc, mw, nw, lane);

    const int g = lane >> 2, tig = lane & 3;
#pragma unroll
    for (int a = 0; a < 2; a++) {
#pragma unroll
        for (int h = 0; h < 2; h++) {
            int grow = t0 + mw * 32 + a * 16 + g + h * 8;
            if (grow < NN) {
                int cc = g_cnt[grow];
                float ic = 1.0f / (float)(cc > 1 ? cc : 1);
#pragma unroll
                for (int q = 0; q < 8; q++) {
                    int col = nw * 64 + q * 8 + 2 * tig;
                    float2 z = *(const float2*)(g_Z + (size_t)grow * D + col);
                    float o0 = acc[a][q][2 * h]     + z.x * ic;
                    float o1 = acc[a][q][2 * h + 1] + z.y * ic;
                    if (use_out) {
                        *(float2*)(outp + (size_t)grow * D + col) = make_float2(o0, o1);
                    } else {
                        o0 = o0 > 0.f ? o0 : 0.f;
                        o1 = o1 > 0.f ? o1 : 0.f;
                        __half hh[2] = {__float2half_rn(o0), __float2half_rn(o1)};
                        *(uint32_t*)(g_Hh + (size_t)grow * D + col) = *(uint32_t*)hh;
                    }
                }
            }
        }
    }
}

// ---------------- host ----------------
extern "C" void kernel_launch(void* const* d_in, const int* in_sizes, int n_in,
                              void* d_out, int out_size) {
    const int*   entity = (const int*)d_in[0];
    const int*   eidx   = (const int*)d_in[1];
    const int*   etype  = (const int*)d_in[2];
    const float* emb    = (const float*)d_in[4];
    const float* W1     = (const float*)d_in[5];
    const float* root1  = (const float*)d_in[6];
    const float* W2     = (const float*)d_in[7];
    const float* root2  = (const float*)d_in[8];
    const int* src = eidx;
    const int* dst = eidx + NE;
    float* out = (float*)d_out;

    static int attr_done = 0;
    if (!attr_done) {
        cudaFuncSetAttribute(k_rgemm_mma,   cudaFuncAttributeMaxDynamicSharedMemorySize, SMEM_RG);
        cudaFuncSetAttribute(k_combine_mma, cudaFuncAttributeMaxDynamicSharedMemorySize, SMEM_CB);
        attr_done = 1;
    }

    int gE = (NE + 255) / 256;
    int gN = (NN + 255) / 256;
    int gZ = (NN * D / 4) / 256;
    int gC = (NN + TE - 1) / TE;

    k_zero_meta<<<gN, 256>>>();
    k_hist<<<gE, 256>>>(etype, dst);
    k_scan<<<1, 1>>>();
    k_sort<<<gE, 256>>>(etype);
    k_prepW<<<34, 256>>>(W1, W2, root1, root2);
    k_gather<<<NN / 8, 256>>>(entity, emb);

    // Layer 1
    k_zeroZ<<<gZ, 256>>>();
    k_rgemm_mma<<<R * NB, 256, SMEM_RG>>>(0, src, dst);
    k_combine_mma<<<gC, 256, SMEM_CB>>>(0, out, 0);

    // Layer 2
    k_zeroZ<<<gZ, 256>>>();
    k_rgemm_mma<<<R * NB, 256, SMEM_RG>>>(1, src, dst);
    k_combine_mma<<<gC, 256, SMEM_CB>>>(1, out, 1);
}